// round 3
// baseline (speedup 1.0000x reference)
#include <cuda_runtime.h>

// DepthToSpace (DCR, block=2): in [16,256,128,128] f32 -> out [16,64,256,256] f32
// out[b, c, 2h+j, 2w+r] = in[b, (2j+r)*64 + c, h, w]
//
// One thread-iteration per output float4 (4 consecutive ow). For a fixed output
// row, elements interleave two contiguous input rows d0=2j*64+c and d1=d0+64:
//   out[4q+0]=in[d0][2q], out[4q+1]=in[d1][2q],
//   out[4q+2]=in[d0][2q+1], out[4q+3]=in[d1][2q+1]
// => two coalesced float2 loads + one coalesced float4 store per iteration.

static constexpr unsigned B  = 16;
static constexpr unsigned D  = 256;   // input channels
static constexpr unsigned C  = 64;    // output channels
static constexpr unsigned H  = 128;
static constexpr unsigned W  = 128;
static constexpr unsigned OH = 256;
static constexpr unsigned OW = 256;
static constexpr unsigned OW4 = OW / 4;                      // 64 float4 per out row
static constexpr unsigned TOTAL_F4 = B * C * OH * OW4;       // 16,777,216
static constexpr unsigned D_STRIDE_F2 = H * W / 2;           // 8192 float2 per input channel
static constexpr unsigned D1_OFF_F2   = C * D_STRIDE_F2;     // +64 channels, float2 units

static constexpr unsigned NBLOCKS  = 4096;
static constexpr unsigned NTHREADS = 256;

__global__ void __launch_bounds__(NTHREADS) d2s_kernel(const float2* __restrict__ in,
                                                       float4* __restrict__ out) {
    const unsigned stride = NBLOCKS * NTHREADS;   // 1,048,576
    for (unsigned idx = blockIdx.x * NTHREADS + threadIdx.x;
         idx < TOTAL_F4; idx += stride) {

        unsigned q  = idx & (OW4 - 1);    // float4 within the output row (w = 2q)
        unsigned t  = idx >> 6;           // /OW4
        unsigned oh = t & (OH - 1);
        t >>= 8;                          // /OH
        unsigned c  = t & (C - 1);
        unsigned b  = t >> 6;             // /C

        unsigned h  = oh >> 1;
        unsigned j  = oh & 1;
        unsigned d0 = (j << 7) + c;       // (2j)*64 + c

        // float2 index of in[b][d0][h][2q]
        unsigned i0 = (b * D + d0) * D_STRIDE_F2 + h * (W / 2) + q;

        float2 a  = in[i0];
        float2 bb = in[i0 + D1_OFF_F2];

        out[idx] = make_float4(a.x, bb.x, a.y, bb.y);
    }
}

extern "C" void kernel_launch(void* const* d_in, const int* in_sizes, int n_in,
                              void* d_out, int out_size) {
    (void)in_sizes; (void)n_in; (void)out_size;
    const float2* in = (const float2*)d_in[0];
    float4* out = (float4*)d_out;
    d2s_kernel<<<NBLOCKS, NTHREADS>>>(in, out);
}

// round 4
// speedup vs baseline: 1.0048x; 1.0048x over previous
#include <cuda_runtime.h>

// DepthToSpace (DCR, block=2): in [16,256,128,128] f32 -> out [16,64,256,256] f32
// out[b, c, 2h+j, 2w+r] = in[b, (2j+r)*64 + c, h, w]
//
// One thread-iteration per 8 consecutive output floats (two float4 stores).
// For a fixed output row, elements interleave two contiguous input rows
// d0 = 2j*64 + c and d1 = d0 + 64:
//   out[8q + 2k]   = in[d0][4q + k]
//   out[8q + 2k+1] = in[d1][4q + k]     k = 0..3
// => two coalesced float4 loads + two contiguous float4 stores per iteration.

static constexpr unsigned B  = 16;
static constexpr unsigned D  = 256;   // input channels
static constexpr unsigned C  = 64;    // output channels
static constexpr unsigned H  = 128;
static constexpr unsigned W  = 128;
static constexpr unsigned OH = 256;
static constexpr unsigned OW = 256;

static constexpr unsigned OW8 = OW / 8;                     // 32 chunks per out row
static constexpr unsigned TOTAL_F8 = B * C * OH * OW8;      // 8,388,608 iterations
static constexpr unsigned D_STRIDE_F4 = H * W / 4;          // 4096 float4 per input channel
static constexpr unsigned D1_OFF_F4   = C * D_STRIDE_F4;    // +64 channels, float4 units

static constexpr unsigned NBLOCKS  = 4096;
static constexpr unsigned NTHREADS = 256;
static constexpr unsigned STRIDE   = NBLOCKS * NTHREADS;    // 1,048,576
static constexpr unsigned NITERS   = TOTAL_F8 / STRIDE;     // exactly 8

__global__ void __launch_bounds__(NTHREADS) d2s_kernel(const float4* __restrict__ in,
                                                       float4* __restrict__ out) {
    unsigned idx = blockIdx.x * NTHREADS + threadIdx.x;

#pragma unroll 4
    for (unsigned it = 0; it < NITERS; ++it, idx += STRIDE) {
        unsigned q  = idx & (OW8 - 1);    // which 8-float chunk in the output row
        unsigned t  = idx >> 5;           // /OW8
        unsigned oh = t & (OH - 1);
        t >>= 8;                          // /OH
        unsigned c  = t & (C - 1);
        unsigned b  = t >> 6;             // /C

        unsigned h  = oh >> 1;
        unsigned j  = oh & 1;
        unsigned d0 = (j << 7) + c;       // (2j)*64 + c

        // float4 index of in[b][d0][h][4q]
        unsigned i0 = (b * D + d0) * D_STRIDE_F4 + h * (W / 4) + q;

        float4 a  = __ldg(&in[i0]);
        float4 bb = __ldg(&in[i0 + D1_OFF_F4]);

        out[2 * idx]     = make_float4(a.x, bb.x, a.y, bb.y);
        out[2 * idx + 1] = make_float4(a.z, bb.z, a.w, bb.w);
    }
}

extern "C" void kernel_launch(void* const* d_in, const int* in_sizes, int n_in,
                              void* d_out, int out_size) {
    (void)in_sizes; (void)n_in; (void)out_size;
    const float4* in = (const float4*)d_in[0];
    float4* out = (float4*)d_out;
    d2s_kernel<<<NBLOCKS, NTHREADS>>>(in, out);
}

// round 5
// speedup vs baseline: 1.0397x; 1.0347x over previous
#include <cuda_runtime.h>
#include <cstdint>

// DepthToSpace (DCR, block=2): in [16,256,128,128] f32 -> out [16,64,256,256] f32
// out[b, c, 2h+j, 2w+r] = in[b, (2j+r)*64 + c, h, w]
//
// One thread-iteration per 8 consecutive output floats. For a fixed output
// row, elements interleave two contiguous input rows d0 = 2j*64 + c and
// d1 = d0 + 64:
//   out[8q + 2k]   = in[d0][4q + k]
//   out[8q + 2k+1] = in[d1][4q + k]     k = 0..3
// => two coalesced 16B loads + ONE contiguous 32B store (st.global.v8.f32,
//    sm_100+) per iteration. Warp store footprint: 1024B contiguous, fully
//    written. Warp load footprint per LDG: 512B contiguous.

static constexpr unsigned B  = 16;
static constexpr unsigned D  = 256;   // input channels
static constexpr unsigned C  = 64;    // output channels
static constexpr unsigned H  = 128;
static constexpr unsigned W  = 128;
static constexpr unsigned OH = 256;
static constexpr unsigned OW = 256;

static constexpr unsigned OW8 = OW / 8;                     // 32 chunks per out row
static constexpr unsigned TOTAL_F8 = B * C * OH * OW8;      // 8,388,608 iterations
static constexpr unsigned D_STRIDE_F4 = H * W / 4;          // 4096 float4 per input channel
static constexpr unsigned D1_OFF_F4   = C * D_STRIDE_F4;    // +64 channels, float4 units

static constexpr unsigned NBLOCKS  = 4096;
static constexpr unsigned NTHREADS = 256;
static constexpr unsigned STRIDE   = NBLOCKS * NTHREADS;    // 1,048,576
static constexpr unsigned NITERS   = TOTAL_F8 / STRIDE;     // exactly 8

__global__ void __launch_bounds__(NTHREADS) d2s_kernel(const float4* __restrict__ in,
                                                       float* __restrict__ out) {
    unsigned idx = blockIdx.x * NTHREADS + threadIdx.x;

#pragma unroll 4
    for (unsigned it = 0; it < NITERS; ++it, idx += STRIDE) {
        unsigned q  = idx & (OW8 - 1);    // which 8-float chunk in the output row
        unsigned t  = idx >> 5;           // /OW8
        unsigned oh = t & (OH - 1);
        t >>= 8;                          // /OH
        unsigned c  = t & (C - 1);
        unsigned b  = t >> 6;             // /C

        unsigned h  = oh >> 1;
        unsigned j  = oh & 1;
        unsigned d0 = (j << 7) + c;       // (2j)*64 + c

        // float4 index of in[b][d0][h][4q]
        unsigned i0 = (b * D + d0) * D_STRIDE_F4 + h * (W / 4) + q;

        float4 a  = __ldg(&in[i0]);
        float4 bb = __ldg(&in[i0 + D1_OFF_F4]);

        // One 256-bit store: out floats [8*idx .. 8*idx+7], interleaved a/bb.
        float* op = out + 8ull * idx;
        asm volatile(
            "st.global.v8.f32 [%0], {%1, %2, %3, %4, %5, %6, %7, %8};"
            :: "l"(op),
               "f"(a.x), "f"(bb.x), "f"(a.y), "f"(bb.y),
               "f"(a.z), "f"(bb.z), "f"(a.w), "f"(bb.w)
            : "memory");
    }
}

extern "C" void kernel_launch(void* const* d_in, const int* in_sizes, int n_in,
                              void* d_out, int out_size) {
    (void)in_sizes; (void)n_in; (void)out_size;
    const float4* in = (const float4*)d_in[0];
    float* out = (float*)d_out;
    d2s_kernel<<<NBLOCKS, NTHREADS>>>(in, out);
}